// round 7
// baseline (speedup 1.0000x reference)
#include <cuda_runtime.h>
#include <cuda_bf16.h>
#include <cstdint>

#define N_TREES     15
#define DEPTH       3
#define INPUT_DIM   128
#define N_CLASSES   10
#define N_LEAVES    8
#define N_INTERNAL  7
#define PER_TREE    983          // 7*128 + 7 + 8*10
#define NODES       105
#define N_PAD       112          // 14 * 8
#define TILE_M      128
#define THREADS     256
#define GRID_P      148          // persistent: one CTA per SM

// ---- smem byte offsets ----
#define OFF_MTAB    0            // 1200 floats = 4800 B
#define OFF_BIAS    4800         // 112 floats = 448 B
#define OFF_BHI     5376         // 112x128 bf16 swizzled = 28672 B
#define OFF_BLO     34048        // 28672 B
#define OFF_AHI     62720        // 128x128 bf16 swizzled = 32768 B
#define OFF_ALO     95488        // 32768 B
#define OFF_ZOUT    120576       // 128*10 floats = 5120 B (inside dead A region)
#define OFF_XST     128256       // 128x128 fp32 stage = 65536 B
#define SMEM_TOTAL  193792
#define Z_STRIDE    113          // odd -> conflict-free per-row reads

#define B_BYTES     28672        // 112 rows * 256 B

// precomputed (setup kernel) converted weights, swizzled identically to smem tiles
__device__ __align__(16) unsigned char gBhi[B_BYTES];
__device__ __align__(16) unsigned char gBlo[B_BYTES];
__device__ float gBias[N_PAD];
__device__ float gMtab[N_TREES * N_LEAVES * N_CLASSES];

// bf16 mma: D += A(row-major m16k16) * B(col-major k16n8)
#define MMA16816(cc, a0, a1, a2, a3, b0, b1) \
    asm volatile("mma.sync.aligned.m16n8k16.row.col.f32.bf16.bf16.f32 " \
        "{%0,%1,%2,%3}, {%4,%5,%6,%7}, {%8,%9}, {%0,%1,%2,%3};" \
        : "+f"((cc)[0]), "+f"((cc)[1]), "+f"((cc)[2]), "+f"((cc)[3]) \
        : "r"(a0), "r"(a1), "r"(a2), "r"(a3), "r"(b0), "r"(b1))

#define LDSM_X4(r0, r1, r2, r3, addr) \
    asm volatile("ldmatrix.sync.aligned.m8n8.x4.shared.b16 {%0,%1,%2,%3}, [%4];" \
        : "=r"(r0), "=r"(r1), "=r"(r2), "=r"(r3) : "r"(addr))

#define CP_ASYNC16(dst, src) \
    asm volatile("cp.async.cg.shared.global [%0], [%1], 16;" \
        :: "r"(dst), "l"(src) : "memory")
#define CP_COMMIT()  asm volatile("cp.async.commit_group;" ::: "memory")
#define CP_WAIT0()   asm volatile("cp.async.wait_group 0;" ::: "memory")

// swizzled byte offset inside a [rows][128 bf16] tile:
//   row*256 + ((chunk ^ (row&7)) * 16) + within-chunk bytes
__device__ __host__ __forceinline__ uint32_t swz(int row, int chunk, int inb) {
    return (uint32_t)(row * 256 + (((chunk) ^ (row & 7)) << 4) + inb);
}

__device__ __forceinline__ uint32_t smem_u32(const void* p) {
    uint32_t a;
    asm("{ .reg .u64 t; cvta.to.shared.u64 t, %1; cvt.u32.u64 %0, t; }"
        : "=r"(a) : "l"(p));
    return a;
}

// ===================== setup kernel: convert W once =====================
__global__ void sdt_setup_kernel(const float* __restrict__ params)
{
    const int tid = threadIdx.x;   // 128 threads

    for (int idx = tid; idx < N_PAD * INPUT_DIM; idx += 128) {
        int row = idx >> 7;
        int col = idx & 127;
        float v = 0.f;
        if (row < NODES) {
            int t = row / N_INTERNAL;
            int n = row - t * N_INTERNAL;
            v = params[t * PER_TREE + n * INPUT_DIM + col];
        }
        __nv_bfloat16 h = __float2bfloat16(v);
        __nv_bfloat16 l = __float2bfloat16(v - __bfloat162float(h));
        uint32_t o = swz(row, col >> 3, (col & 7) << 1);
        *reinterpret_cast<__nv_bfloat16*>(gBhi + o) = h;
        *reinterpret_cast<__nv_bfloat16*>(gBlo + o) = l;
    }
    if (tid < N_PAD) {
        float v = 0.f;
        if (tid < NODES) {
            int t = tid / N_INTERNAL;
            int n = tid - t * N_INTERNAL;
            v = params[t * PER_TREE + N_INTERNAL * INPUT_DIM + n];
        }
        gBias[tid] = v;
    }
    if (tid < N_TREES * N_LEAVES) {
        int t = tid / N_LEAVES;
        int l = tid - t * N_LEAVES;
        const float* twl = params + N_TREES * PER_TREE;
        float mx = twl[0];
        #pragma unroll
        for (int i = 1; i < N_TREES; ++i) mx = fmaxf(mx, twl[i]);
        float s = 0.f;
        #pragma unroll
        for (int i = 0; i < N_TREES; ++i) s += __expf(twl[i] - mx);
        float tw = __expf(twl[t] - mx) / s;

        const float* ll = params + t * PER_TREE + N_INTERNAL * INPUT_DIM + N_INTERNAL
                        + l * N_CLASSES;
        float m2 = ll[0];
        #pragma unroll
        for (int c = 1; c < N_CLASSES; ++c) m2 = fmaxf(m2, ll[c]);
        float e[N_CLASSES];
        float s2 = 0.f;
        #pragma unroll
        for (int c = 0; c < N_CLASSES; ++c) { e[c] = __expf(ll[c] - m2); s2 += e[c]; }
        float inv = tw / s2;
        #pragma unroll
        for (int c = 0; c < N_CLASSES; ++c)
            gMtab[(t * N_LEAVES + l) * N_CLASSES + c] = e[c] * inv;
    }
}

// ===================== main kernel =====================
__global__ __launch_bounds__(THREADS, 1)
void sdt_mma_kernel(const float* __restrict__ x,
                    float* __restrict__ out,
                    int batch)
{
    extern __shared__ char smem[];
    const uint32_t sb = smem_u32(smem);
    const int tid  = threadIdx.x;
    const int lane = tid & 31;
    const int w    = tid >> 5;        // 0..7, warp owns rows w*16..w*16+15
    const int ntiles = batch >> 7;

    // ---- copy precomputed B_hi/B_lo, Mtab, bias into smem (once) ----
    {
        const uint4* srcH = reinterpret_cast<const uint4*>(gBhi);
        const uint4* srcL = reinterpret_cast<const uint4*>(gBlo);
        uint4* dstH = reinterpret_cast<uint4*>(smem + OFF_BHI);
        uint4* dstL = reinterpret_cast<uint4*>(smem + OFF_BLO);
        #pragma unroll
        for (int i = 0; i < B_BYTES / 16 / THREADS; ++i) {
            dstH[tid + i * THREADS] = srcH[tid + i * THREADS];
            dstL[tid + i * THREADS] = srcL[tid + i * THREADS];
        }
        float* msm = reinterpret_cast<float*>(smem + OFF_MTAB);
        for (int i = tid; i < N_TREES * N_LEAVES * N_CLASSES; i += THREADS)
            msm[i] = gMtab[i];
        float* bsm = reinterpret_cast<float*>(smem + OFF_BIAS);
        if (tid < N_PAD) bsm[tid] = gBias[tid];
    }

    // ---- prologue: stage + convert first tile ----
    {
        const char* src = reinterpret_cast<const char*>(x)
                        + (size_t)blockIdx.x * TILE_M * INPUT_DIM * 4;
        #pragma unroll
        for (int i = 0; i < 16; ++i) {
            uint32_t off = (uint32_t)(tid + i * THREADS) * 16;
            CP_ASYNC16(sb + OFF_XST + off, src + off);
        }
        CP_COMMIT();
        CP_WAIT0();
        __syncthreads();
        // convert x_stage -> A_hi/A_lo
        const float4* xs = reinterpret_cast<const float4*>(smem + OFF_XST);
        #pragma unroll
        for (int it = 0; it < 16; ++it) {
            int idx = tid + it * THREADS;
            int r  = idx >> 5;
            int c4 = idx & 31;
            float4 v = xs[idx];
            __nv_bfloat16 h0 = __float2bfloat16(v.x);
            __nv_bfloat16 h1 = __float2bfloat16(v.y);
            __nv_bfloat16 h2 = __float2bfloat16(v.z);
            __nv_bfloat16 h3 = __float2bfloat16(v.w);
            __nv_bfloat16 l0 = __float2bfloat16(v.x - __bfloat162float(h0));
            __nv_bfloat16 l1 = __float2bfloat16(v.y - __bfloat162float(h1));
            __nv_bfloat16 l2 = __float2bfloat16(v.z - __bfloat162float(h2));
            __nv_bfloat16 l3 = __float2bfloat16(v.w - __bfloat162float(h3));
            uint32_t base = swz(r, c4 >> 1, (c4 & 1) << 3);
            *reinterpret_cast<__nv_bfloat162*>(smem + OFF_AHI + base)     = __nv_bfloat162(h0, h1);
            *reinterpret_cast<__nv_bfloat162*>(smem + OFF_AHI + base + 4) = __nv_bfloat162(h2, h3);
            *reinterpret_cast<__nv_bfloat162*>(smem + OFF_ALO + base)     = __nv_bfloat162(l0, l1);
            *reinterpret_cast<__nv_bfloat162*>(smem + OFF_ALO + base + 4) = __nv_bfloat162(l2, l3);
        }
        __syncthreads();
    }

    // ldmatrix lane-address precompute
    const int arow     = w * 16 + ((lane >> 3) & 1) * 8 + (lane & 7);
    const int apar     = lane >> 4;
    const uint32_t arow256 = (uint32_t)arow * 256;
    const int arow7    = arow & 7;
    const int brow_local = ((lane >> 4) & 1) * 8 + (lane & 7);
    const int bpar     = (lane >> 3) & 1;

    const uint32_t sBHI = sb + OFF_BHI;
    const uint32_t sBLO = sb + OFF_BLO;
    const uint32_t sAHI = sb + OFF_AHI;
    const uint32_t sALO = sb + OFF_ALO;

    // ==================== persistent tile loop ====================
    for (int tile = blockIdx.x; tile < ntiles; tile += GRID_P) {
        const int next = tile + GRID_P;

        // prefetch next x tile into stage (overlaps with MMA below)
        if (next < ntiles) {
            const char* src = reinterpret_cast<const char*>(x)
                            + (size_t)next * TILE_M * INPUT_DIM * 4;
            #pragma unroll
            for (int i = 0; i < 16; ++i) {
                uint32_t off = (uint32_t)(tid + i * THREADS) * 16;
                CP_ASYNC16(sb + OFF_XST + off, src + off);
            }
            CP_COMMIT();
        }

        // ---- 3-pass bf16-split HMMA ----
        float cc[14][4];
        #pragma unroll
        for (int nt = 0; nt < 14; ++nt)
            #pragma unroll
            for (int i = 0; i < 4; ++i) cc[nt][i] = 0.f;

        #pragma unroll 1
        for (int pass = 0; pass < 3; ++pass) {
            const uint32_t Ab = (pass == 1) ? sALO : sAHI;   // Ah, Al, Ah
            const uint32_t Bb = (pass == 2) ? sBLO : sBHI;   // Bh, Bh, Bl
            #pragma unroll
            for (int ks = 0; ks < 8; ++ks) {
                const int ch  = ks * 2;
                const int ach = ch + apar;
                uint32_t a0, a1, a2, a3;
                LDSM_X4(a0, a1, a2, a3, Ab + arow256 + ((ach ^ arow7) << 4));
                #pragma unroll
                for (int j = 0; j < 7; ++j) {
                    int brow = j * 16 + brow_local;
                    int bch  = ch + bpar;
                    uint32_t b0A, b1A, b0B, b1B;
                    LDSM_X4(b0A, b1A, b0B, b1B,
                            Bb + brow * 256 + ((bch ^ (brow & 7)) << 4));
                    MMA16816(cc[2 * j],     a0, a1, a2, a3, b0A, b1A);
                    MMA16816(cc[2 * j + 1], a0, a1, a2, a3, b0B, b1B);
                }
            }
        }

        // ---- scatter accumulators to z tile (A region is dead now) ----
        __syncthreads();
        float* zsm = reinterpret_cast<float*>(smem + OFF_AHI);
        {
            const int row   = w * 16 + (lane >> 2);
            const int cbase = (lane & 3) << 1;
            #pragma unroll
            for (int nt = 0; nt < 14; ++nt) {
                int col = nt * 8 + cbase;
                zsm[row * Z_STRIDE + col]           = cc[nt][0];
                zsm[row * Z_STRIDE + col + 1]       = cc[nt][1];
                zsm[(row + 8) * Z_STRIDE + col]     = cc[nt][2];
                zsm[(row + 8) * Z_STRIDE + col + 1] = cc[nt][3];
            }
        }
        __syncthreads();

        // ---- per-row tree epilogue (threads 0..127) ----
        if (tid < TILE_M) {
            const float* Msm = reinterpret_cast<const float*>(smem + OFF_MTAB);
            const float* bsm = reinterpret_cast<const float*>(smem + OFF_BIAS);
            float* osm = reinterpret_cast<float*>(smem + OFF_ZOUT);

            float acc[N_CLASSES];
            #pragma unroll
            for (int c = 0; c < N_CLASSES; ++c) acc[c] = 0.f;

            const float* zrow = zsm + tid * Z_STRIDE;
            #pragma unroll
            for (int t = 0; t < N_TREES; ++t) {
                float p_[N_INTERNAL], q_[N_INTERNAL];
                #pragma unroll
                for (int n = 0; n < N_INTERNAL; ++n) {
                    float zz = zrow[t * N_INTERNAL + n] + bsm[t * N_INTERNAL + n];
                    float e  = __expf(-zz);
                    float pp = 1.f / (1.f + e);
                    p_[n] = pp;
                    q_[n] = e * pp;
                }
                float tp[N_LEAVES];
                #pragma unroll
                for (int l = 0; l < N_LEAVES; ++l) {
                    int node = l + N_INTERNAL;
                    float prob = 1.f;
                    #pragma unroll
                    for (int d = 0; d < DEPTH; ++d) {
                        int par = (node - 1) >> 1;
                        prob *= (node & 1) ? q_[par] : p_[par];
                        node = par;
                    }
                    tp[l] = prob;
                }
                const float* Mt = Msm + t * N_LEAVES * N_CLASSES;
                #pragma unroll
                for (int l = 0; l < N_LEAVES; ++l) {
                    #pragma unroll
                    for (int c = 0; c < N_CLASSES; ++c)
                        acc[c] = fmaf(tp[l], Mt[l * N_CLASSES + c], acc[c]);
                }
            }
            #pragma unroll
            for (int c = 0; c < N_CLASSES; ++c)
                osm[tid * N_CLASSES + c] = acc[c];
        }
        __syncthreads();

        // ---- coalesced output copy ----
        {
            const uint4* osv = reinterpret_cast<const uint4*>(smem + OFF_ZOUT);
            uint4* og = reinterpret_cast<uint4*>(out + (size_t)tile * TILE_M * N_CLASSES);
            #pragma unroll
            for (int i = tid; i < TILE_M * N_CLASSES / 4; i += THREADS)
                og[i] = osv[i];
        }
        __syncthreads();

        // ---- convert staged x for next tile into A buffers ----
        if (next < ntiles) {
            CP_WAIT0();
            __syncthreads();
            const float4* xs = reinterpret_cast<const float4*>(smem + OFF_XST);
            #pragma unroll
            for (int it = 0; it < 16; ++it) {
                int idx = tid + it * THREADS;
                int r  = idx >> 5;
                int c4 = idx & 31;
                float4 v = xs[idx];
                __nv_bfloat16 h0 = __float2bfloat16(v.x);
                __nv_bfloat16 h1 = __float2bfloat16(v.y);
                __nv_bfloat16 h2 = __float2bfloat16(v.z);
                __nv_bfloat16 h3 = __float2bfloat16(v.w);
                __nv_bfloat16 l0 = __float2bfloat16(v.x - __bfloat162float(h0));
                __nv_bfloat16 l1 = __float2bfloat16(v.y - __bfloat162float(h1));
                __nv_bfloat16 l2 = __float2bfloat16(v.z - __bfloat162float(h2));
                __nv_bfloat16 l3 = __float2bfloat16(v.w - __bfloat162float(h3));
                uint32_t base = swz(r, c4 >> 1, (c4 & 1) << 3);
                *reinterpret_cast<__nv_bfloat162*>(smem + OFF_AHI + base)     = __nv_bfloat162(h0, h1);
                *reinterpret_cast<__nv_bfloat162*>(smem + OFF_AHI + base + 4) = __nv_bfloat162(h2, h3);
                *reinterpret_cast<__nv_bfloat162*>(smem + OFF_ALO + base)     = __nv_bfloat162(l0, l1);
                *reinterpret_cast<__nv_bfloat162*>(smem + OFF_ALO + base + 4) = __nv_bfloat162(l2, l3);
            }
            __syncthreads();
        }
    }
}

extern "C" void kernel_launch(void* const* d_in, const int* in_sizes, int n_in,
                              void* d_out, int out_size)
{
    const float* x      = (const float*)d_in[0];
    const float* params = (const float*)d_in[1];
    float* out          = (float*)d_out;

    int batch = in_sizes[0] / INPUT_DIM;

    cudaFuncSetAttribute(sdt_mma_kernel,
                         cudaFuncAttributeMaxDynamicSharedMemorySize,
                         SMEM_TOTAL);

    sdt_setup_kernel<<<1, 128>>>(params);

    sdt_mma_kernel<<<GRID_P, THREADS, SMEM_TOTAL>>>(x, out, batch);
}

// round 8
// speedup vs baseline: 1.1733x; 1.1733x over previous
#include <cuda_runtime.h>
#include <cuda_bf16.h>
#include <cstdint>

#define N_TREES     15
#define DEPTH       3
#define INPUT_DIM   128
#define N_CLASSES   10
#define N_LEAVES    8
#define N_INTERNAL  7
#define PER_TREE    983          // 7*128 + 7 + 8*10
#define NODES       105
#define N_PAD       112          // 14 * 8
#define TILE_M      96
#define THREADS     384          // 12 warps: 6 M-groups x 2 N-halves

// ---- smem byte offsets ----
#define OFF_MTAB    0            // 1200 floats = 4800 B
#define OFF_BIAS    4800         // 112 floats = 448 B
#define OFF_BHI     5376         // 112x128 bf16 swizzled = 28672 B
#define OFF_BLO     34048        // 28672 B
#define OFF_AHI     62720        // 96x128 bf16 swizzled = 24576 B
#define OFF_ALO     87296        // 24576 B
#define SMEM_TOTAL  111872
// z tile overlays A_hi/A_lo after MMA: 96*113*4 = 43392 B at OFF_AHI
#define OFF_ZOUT    (OFF_AHI + 43392)   // 96*10 floats = 3840 B
#define Z_STRIDE    113          // odd -> conflict-free per-row reads

#define B_BYTES     28672        // 112 rows * 256 B

// precomputed (setup kernel) converted weights, swizzled identically to smem tiles
__device__ __align__(16) unsigned char gBhi[B_BYTES];
__device__ __align__(16) unsigned char gBlo[B_BYTES];
__device__ float gBias[N_PAD];
__device__ float gMtab[N_TREES * N_LEAVES * N_CLASSES];

// bf16 mma: D += A(row-major m16k16) * B(col-major k16n8)
#define MMA16816(cc, a0, a1, a2, a3, b0, b1) \
    asm volatile("mma.sync.aligned.m16n8k16.row.col.f32.bf16.bf16.f32 " \
        "{%0,%1,%2,%3}, {%4,%5,%6,%7}, {%8,%9}, {%0,%1,%2,%3};" \
        : "+f"((cc)[0]), "+f"((cc)[1]), "+f"((cc)[2]), "+f"((cc)[3]) \
        : "r"(a0), "r"(a1), "r"(a2), "r"(a3), "r"(b0), "r"(b1))

#define LDSM_X4(r0, r1, r2, r3, addr) \
    asm volatile("ldmatrix.sync.aligned.m8n8.x4.shared.b16 {%0,%1,%2,%3}, [%4];" \
        : "=r"(r0), "=r"(r1), "=r"(r2), "=r"(r3) : "r"(addr))

#define LDSM_X2(r0, r1, addr) \
    asm volatile("ldmatrix.sync.aligned.m8n8.x2.shared.b16 {%0,%1}, [%2];" \
        : "=r"(r0), "=r"(r1) : "r"(addr))

// swizzled byte offset inside a [rows][128 bf16] tile:
//   row*256 + ((chunk ^ (row&7)) * 16) + within-chunk bytes
__device__ __host__ __forceinline__ uint32_t swz(int row, int chunk, int inb) {
    return (uint32_t)(row * 256 + (((chunk) ^ (row & 7)) << 4) + inb);
}

__device__ __forceinline__ uint32_t smem_u32(const void* p) {
    uint32_t a;
    asm("{ .reg .u64 t; cvta.to.shared.u64 t, %1; cvt.u32.u64 %0, t; }"
        : "=r"(a) : "l"(p));
    return a;
}

// ===================== setup kernel: convert W once =====================
__global__ void sdt_setup_kernel(const float* __restrict__ params)
{
    const int tid = threadIdx.x;   // 128 threads

    for (int idx = tid; idx < N_PAD * INPUT_DIM; idx += 128) {
        int row = idx >> 7;
        int col = idx & 127;
        float v = 0.f;
        if (row < NODES) {
            int t = row / N_INTERNAL;
            int n = row - t * N_INTERNAL;
            v = params[t * PER_TREE + n * INPUT_DIM + col];
        }
        __nv_bfloat16 h = __float2bfloat16(v);
        __nv_bfloat16 l = __float2bfloat16(v - __bfloat162float(h));
        uint32_t o = swz(row, col >> 3, (col & 7) << 1);
        *reinterpret_cast<__nv_bfloat16*>(gBhi + o) = h;
        *reinterpret_cast<__nv_bfloat16*>(gBlo + o) = l;
    }
    if (tid < N_PAD) {
        float v = 0.f;
        if (tid < NODES) {
            int t = tid / N_INTERNAL;
            int n = tid - t * N_INTERNAL;
            v = params[t * PER_TREE + N_INTERNAL * INPUT_DIM + n];
        }
        gBias[tid] = v;
    }
    if (tid < N_TREES * N_LEAVES) {
        int t = tid / N_LEAVES;
        int l = tid - t * N_LEAVES;
        const float* twl = params + N_TREES * PER_TREE;
        float mx = twl[0];
        #pragma unroll
        for (int i = 1; i < N_TREES; ++i) mx = fmaxf(mx, twl[i]);
        float s = 0.f;
        #pragma unroll
        for (int i = 0; i < N_TREES; ++i) s += __expf(twl[i] - mx);
        float tw = __expf(twl[t] - mx) / s;

        const float* ll = params + t * PER_TREE + N_INTERNAL * INPUT_DIM + N_INTERNAL
                        + l * N_CLASSES;
        float m2 = ll[0];
        #pragma unroll
        for (int c = 1; c < N_CLASSES; ++c) m2 = fmaxf(m2, ll[c]);
        float e[N_CLASSES];
        float s2 = 0.f;
        #pragma unroll
        for (int c = 0; c < N_CLASSES; ++c) { e[c] = __expf(ll[c] - m2); s2 += e[c]; }
        float inv = tw / s2;
        #pragma unroll
        for (int c = 0; c < N_CLASSES; ++c)
            gMtab[(t * N_LEAVES + l) * N_CLASSES + c] = e[c] * inv;
    }
}

// ===================== main kernel =====================
__global__ __launch_bounds__(THREADS, 2)
void sdt_mma_kernel(const float* __restrict__ x,
                    float* __restrict__ out,
                    int batch)
{
    extern __shared__ char smem[];
    const uint32_t sb = smem_u32(smem);
    const int tid  = threadIdx.x;
    const int lane = tid & 31;
    const int w    = tid >> 5;         // 0..11
    const int mg   = w >> 1;           // 0..5: M-group (rows mg*16..mg*16+15)
    const int nh   = w & 1;            // 0/1:  N-half (cols nh*56..nh*56+55)

    // ---- copy precomputed B_hi/B_lo, Mtab, bias into smem ----
    {
        const uint4* srcH = reinterpret_cast<const uint4*>(gBhi);
        const uint4* srcL = reinterpret_cast<const uint4*>(gBlo);
        uint4* dstH = reinterpret_cast<uint4*>(smem + OFF_BHI);
        uint4* dstL = reinterpret_cast<uint4*>(smem + OFF_BLO);
        for (int i = tid; i < B_BYTES / 16; i += THREADS) {
            dstH[i] = srcH[i];
            dstL[i] = srcL[i];
        }
        float* msm = reinterpret_cast<float*>(smem + OFF_MTAB);
        for (int i = tid; i < N_TREES * N_LEAVES * N_CLASSES; i += THREADS)
            msm[i] = gMtab[i];
        float* bsm = reinterpret_cast<float*>(smem + OFF_BIAS);
        if (tid < N_PAD) bsm[tid] = gBias[tid];
    }

    // ---- stage A: x tile -> bf16 hi/lo, swizzled (rows clamped at batch-1) ----
    {
        const int base = blockIdx.x * TILE_M;
        #pragma unroll
        for (int it = 0; it < TILE_M * (INPUT_DIM / 4) / THREADS; ++it) {
            int idx = tid + it * THREADS;
            int r  = idx >> 5;
            int c4 = idx & 31;
            int rg = base + r;
            if (rg >= batch) rg = batch - 1;
            float4 v = reinterpret_cast<const float4*>(x)[(size_t)rg * 32 + c4];
            __nv_bfloat16 h0 = __float2bfloat16(v.x);
            __nv_bfloat16 h1 = __float2bfloat16(v.y);
            __nv_bfloat16 h2 = __float2bfloat16(v.z);
            __nv_bfloat16 h3 = __float2bfloat16(v.w);
            __nv_bfloat16 l0 = __float2bfloat16(v.x - __bfloat162float(h0));
            __nv_bfloat16 l1 = __float2bfloat16(v.y - __bfloat162float(h1));
            __nv_bfloat16 l2 = __float2bfloat16(v.z - __bfloat162float(h2));
            __nv_bfloat16 l3 = __float2bfloat16(v.w - __bfloat162float(h3));
            uint32_t basew = swz(r, c4 >> 1, (c4 & 1) << 3);
            *reinterpret_cast<__nv_bfloat162*>(smem + OFF_AHI + basew)     = __nv_bfloat162(h0, h1);
            *reinterpret_cast<__nv_bfloat162*>(smem + OFF_AHI + basew + 4) = __nv_bfloat162(h2, h3);
            *reinterpret_cast<__nv_bfloat162*>(smem + OFF_ALO + basew)     = __nv_bfloat162(l0, l1);
            *reinterpret_cast<__nv_bfloat162*>(smem + OFF_ALO + basew + 4) = __nv_bfloat162(l2, l3);
        }
    }
    __syncthreads();

    // ================= 3-pass bf16-split HMMA mainloop =================
    // A x4: m0=rows0-7(ch+apar) m1=rows8-15(ch+apar) m2/m3 same at ch+1
    const int arow   = mg * 16 + ((lane >> 3) & 1) * 8 + (lane & 7);
    const int apar   = lane >> 4;
    const uint32_t arow256 = (uint32_t)arow * 256;
    const int arow7  = arow & 7;
    // B x4 pair j: m0=(nt=2j,ch) m1=(nt=2j,ch+1) m2=(nt=2j+1,ch) m3=(nt=2j+1,ch+1)
    const int nbase  = nh * 56;
    const int brow_local = ((lane >> 4) & 1) * 8 + (lane & 7);
    const int bpar   = (lane >> 3) & 1;
    // B x2 (nt=6): m0 rows@ch (lanes0-7), m1 rows@ch+1 (lanes8-15)
    const int brow2  = nbase + 48 + (lane & 7);
    const int bpar2  = (lane >> 3) & 1;

    float cc[7][4];
    #pragma unroll
    for (int nt = 0; nt < 7; ++nt)
        #pragma unroll
        for (int i = 0; i < 4; ++i) cc[nt][i] = 0.f;

    const uint32_t sBHI = sb + OFF_BHI;
    const uint32_t sBLO = sb + OFF_BLO;
    const uint32_t sAHI = sb + OFF_AHI;
    const uint32_t sALO = sb + OFF_ALO;

    #pragma unroll 1
    for (int pass = 0; pass < 3; ++pass) {
        const uint32_t Ab = (pass == 1) ? sALO : sAHI;   // Ah, Al, Ah
        const uint32_t Bb = (pass == 2) ? sBLO : sBHI;   // Bh, Bh, Bl
        #pragma unroll
        for (int ks = 0; ks < 8; ++ks) {
            const int ch = ks * 2;
            uint32_t a0, a1, a2, a3;
            LDSM_X4(a0, a1, a2, a3, Ab + arow256 + (((ch + apar) ^ arow7) << 4));
            #pragma unroll
            for (int j = 0; j < 3; ++j) {
                int brow = nbase + j * 16 + brow_local;
                int bch  = ch + bpar;
                uint32_t b0A, b1A, b0B, b1B;
                LDSM_X4(b0A, b1A, b0B, b1B,
                        Bb + brow * 256 + ((bch ^ (brow & 7)) << 4));
                MMA16816(cc[2 * j],     a0, a1, a2, a3, b0A, b1A);
                MMA16816(cc[2 * j + 1], a0, a1, a2, a3, b0B, b1B);
            }
            {
                uint32_t b0, b1;
                int bch = ch + bpar2;
                LDSM_X2(b0, b1, Bb + brow2 * 256 + ((bch ^ (brow2 & 7)) << 4));
                MMA16816(cc[6], a0, a1, a2, a3, b0, b1);
            }
        }
    }

    // ---- scatter accumulators to z tile (A region dead now) ----
    __syncthreads();
    float* zsm = reinterpret_cast<float*>(smem + OFF_AHI);
    {
        const int row   = mg * 16 + (lane >> 2);
        const int cbase = nbase + ((lane & 3) << 1);
        #pragma unroll
        for (int nt = 0; nt < 7; ++nt) {
            int col = nt * 8 + cbase;
            zsm[row * Z_STRIDE + col]           = cc[nt][0];
            zsm[row * Z_STRIDE + col + 1]       = cc[nt][1];
            zsm[(row + 8) * Z_STRIDE + col]     = cc[nt][2];
            zsm[(row + 8) * Z_STRIDE + col + 1] = cc[nt][3];
        }
    }
    __syncthreads();

    // ---- per-row tree epilogue (threads 0..95) ----
    if (tid < TILE_M) {
        const float* Msm = reinterpret_cast<const float*>(smem + OFF_MTAB);
        const float* bsm = reinterpret_cast<const float*>(smem + OFF_BIAS);
        float* osm = reinterpret_cast<float*>(smem + OFF_ZOUT);

        float acc[N_CLASSES];
        #pragma unroll
        for (int c = 0; c < N_CLASSES; ++c) acc[c] = 0.f;

        const float* zrow = zsm + tid * Z_STRIDE;
        #pragma unroll
        for (int t = 0; t < N_TREES; ++t) {
            float p_[N_INTERNAL], q_[N_INTERNAL];
            #pragma unroll
            for (int n = 0; n < N_INTERNAL; ++n) {
                float zz = zrow[t * N_INTERNAL + n] + bsm[t * N_INTERNAL + n];
                float e  = __expf(-zz);
                float pp = 1.f / (1.f + e);
                p_[n] = pp;
                q_[n] = e * pp;
            }
            float tp[N_LEAVES];
            #pragma unroll
            for (int l = 0; l < N_LEAVES; ++l) {
                int node = l + N_INTERNAL;
                float prob = 1.f;
                #pragma unroll
                for (int d = 0; d < DEPTH; ++d) {
                    int par = (node - 1) >> 1;
                    prob *= (node & 1) ? q_[par] : p_[par];
                    node = par;
                }
                tp[l] = prob;
            }
            const float* Mt = Msm + t * N_LEAVES * N_CLASSES;
            #pragma unroll
            for (int l = 0; l < N_LEAVES; ++l) {
                #pragma unroll
                for (int c = 0; c < N_CLASSES; ++c)
                    acc[c] = fmaf(tp[l], Mt[l * N_CLASSES + c], acc[c]);
            }
        }
        #pragma unroll
        for (int c = 0; c < N_CLASSES; ++c)
            osm[tid * N_CLASSES + c] = acc[c];
    }
    __syncthreads();

    // ---- coalesced output copy (handles ragged last tile) ----
    {
        const int base = blockIdx.x * TILE_M;
        int valid = batch - base;
        if (valid > TILE_M) valid = TILE_M;
        const int tot4 = valid * N_CLASSES / 4;
        const uint4* osv = reinterpret_cast<const uint4*>(smem + OFF_ZOUT);
        uint4* og = reinterpret_cast<uint4*>(out + (size_t)base * N_CLASSES);
        for (int i = tid; i < tot4; i += THREADS) og[i] = osv[i];
    }
}

extern "C" void kernel_launch(void* const* d_in, const int* in_sizes, int n_in,
                              void* d_out, int out_size)
{
    const float* x      = (const float*)d_in[0];
    const float* params = (const float*)d_in[1];
    float* out          = (float*)d_out;

    int batch = in_sizes[0] / INPUT_DIM;

    cudaFuncSetAttribute(sdt_mma_kernel,
                         cudaFuncAttributeMaxDynamicSharedMemorySize,
                         SMEM_TOTAL);

    sdt_setup_kernel<<<1, 128>>>(params);

    int grid = (batch + TILE_M - 1) / TILE_M;
    sdt_mma_kernel<<<grid, THREADS, SMEM_TOTAL>>>(x, out, batch);
}

// round 9
// speedup vs baseline: 1.5528x; 1.3234x over previous
#include <cuda_runtime.h>
#include <cuda_bf16.h>
#include <cstdint>

#define N_TREES     15
#define DEPTH       3
#define INPUT_DIM   128
#define N_CLASSES   10
#define N_LEAVES    8
#define N_INTERNAL  7
#define PER_TREE    983          // 7*128 + 7 + 8*10
#define NODES       105
#define N_PAD       112          // 14 * 8
#define TILE_M      128
#define THREADS     256          // 8 warps: 4 M-groups(M=32) x 2 N-halves(N=56)
#define M_STRIDE    12           // padded leaf-class row (10 -> 12 for float4)

// ---- smem byte offsets ----
#define OFF_MTAB    0            // 15*8*12 floats = 5760 B
#define OFF_BIAS    5760         // 112 floats = 448 B
#define OFF_BHI     6272         // 112x128 bf16 swizzled = 28672 B
#define OFF_AHI     34944        // 128x128 bf16 swizzled = 32768 B
#define OFF_ALO     67712        // 32768 B (A_lo; reused for B_lo in pass 2)
#define SMEM_TOTAL  100480
// overlays after mainloop:
#define OFF_ZS      OFF_AHI      // z tile 128*113*4 = 57856 B
#define OFF_OSM     OFF_BHI      // 2*128*10 floats = 10240 B (B_hi dead)
#define Z_STRIDE    113

#define B_BYTES     28672        // 112 rows * 256 B

__device__ __align__(16) unsigned char gBhi[B_BYTES];
__device__ __align__(16) unsigned char gBlo[B_BYTES];
__device__ float gBias[N_PAD];
__device__ __align__(16) float gMtab[N_TREES * N_LEAVES * M_STRIDE];

#define MMA16816(cc, a0, a1, a2, a3, b0, b1) \
    asm volatile("mma.sync.aligned.m16n8k16.row.col.f32.bf16.bf16.f32 " \
        "{%0,%1,%2,%3}, {%4,%5,%6,%7}, {%8,%9}, {%0,%1,%2,%3};" \
        : "+f"((cc)[0]), "+f"((cc)[1]), "+f"((cc)[2]), "+f"((cc)[3]) \
        : "r"(a0), "r"(a1), "r"(a2), "r"(a3), "r"(b0), "r"(b1))

#define LDSM_X4(r0, r1, r2, r3, addr) \
    asm volatile("ldmatrix.sync.aligned.m8n8.x4.shared.b16 {%0,%1,%2,%3}, [%4];" \
        : "=r"(r0), "=r"(r1), "=r"(r2), "=r"(r3) : "r"(addr))

#define LDSM_X2(r0, r1, addr) \
    asm volatile("ldmatrix.sync.aligned.m8n8.x2.shared.b16 {%0,%1}, [%2];" \
        : "=r"(r0), "=r"(r1) : "r"(addr))

// swizzled byte offset inside a [rows][128 bf16] tile
__device__ __host__ __forceinline__ uint32_t swz(int row, int chunk, int inb) {
    return (uint32_t)(row * 256 + (((chunk) ^ (row & 7)) << 4) + inb);
}

__device__ __forceinline__ uint32_t smem_u32(const void* p) {
    uint32_t a;
    asm("{ .reg .u64 t; cvta.to.shared.u64 t, %1; cvt.u32.u64 %0, t; }"
        : "=r"(a) : "l"(p));
    return a;
}

// ===================== setup kernel: convert W once =====================
__global__ void sdt_setup_kernel(const float* __restrict__ params)
{
    const int tid = threadIdx.x;   // 128 threads

    for (int idx = tid; idx < N_PAD * INPUT_DIM; idx += 128) {
        int row = idx >> 7;
        int col = idx & 127;
        float v = 0.f;
        if (row < NODES) {
            int t = row / N_INTERNAL;
            int n = row - t * N_INTERNAL;
            v = params[t * PER_TREE + n * INPUT_DIM + col];
        }
        __nv_bfloat16 h = __float2bfloat16(v);
        __nv_bfloat16 l = __float2bfloat16(v - __bfloat162float(h));
        uint32_t o = swz(row, col >> 3, (col & 7) << 1);
        *reinterpret_cast<__nv_bfloat16*>(gBhi + o) = h;
        *reinterpret_cast<__nv_bfloat16*>(gBlo + o) = l;
    }
    if (tid < N_PAD) {
        float v = 0.f;
        if (tid < NODES) {
            int t = tid / N_INTERNAL;
            int n = tid - t * N_INTERNAL;
            v = params[t * PER_TREE + N_INTERNAL * INPUT_DIM + n];
        }
        gBias[tid] = v;
    }
    if (tid < N_TREES * N_LEAVES) {
        int t = tid / N_LEAVES;
        int l = tid - t * N_LEAVES;
        const float* twl = params + N_TREES * PER_TREE;
        float mx = twl[0];
        #pragma unroll
        for (int i = 1; i < N_TREES; ++i) mx = fmaxf(mx, twl[i]);
        float s = 0.f;
        #pragma unroll
        for (int i = 0; i < N_TREES; ++i) s += __expf(twl[i] - mx);
        float tw = __expf(twl[t] - mx) / s;

        const float* ll = params + t * PER_TREE + N_INTERNAL * INPUT_DIM + N_INTERNAL
                        + l * N_CLASSES;
        float m2 = ll[0];
        #pragma unroll
        for (int c = 1; c < N_CLASSES; ++c) m2 = fmaxf(m2, ll[c]);
        float e[N_CLASSES];
        float s2 = 0.f;
        #pragma unroll
        for (int c = 0; c < N_CLASSES; ++c) { e[c] = __expf(ll[c] - m2); s2 += e[c]; }
        float inv = tw / s2;
        #pragma unroll
        for (int c = 0; c < N_CLASSES; ++c)
            gMtab[(t * N_LEAVES + l) * M_STRIDE + c] = e[c] * inv;
        gMtab[(t * N_LEAVES + l) * M_STRIDE + 10] = 0.f;
        gMtab[(t * N_LEAVES + l) * M_STRIDE + 11] = 0.f;
    }
}

// ---- tree epilogue over trees [T0, T1) for one row ----
template<int T0, int T1>
__device__ __forceinline__ void tree_epi(const float* __restrict__ zrow,
                                         const float* __restrict__ bsm,
                                         const float* __restrict__ Msm,
                                         float* __restrict__ accout)
{
    float acc[N_CLASSES];
    #pragma unroll
    for (int c = 0; c < N_CLASSES; ++c) acc[c] = 0.f;

    #pragma unroll
    for (int t = T0; t < T1; ++t) {
        float p_[N_INTERNAL], q_[N_INTERNAL];
        #pragma unroll
        for (int n = 0; n < N_INTERNAL; ++n) {
            float zz = zrow[t * N_INTERNAL + n] + bsm[t * N_INTERNAL + n];
            float e  = __expf(-zz);
            float pp = 1.f / (1.f + e);   // sigmoid(z)  -> right
            p_[n] = pp;
            q_[n] = e * pp;               // sigmoid(-z) -> left
        }
        float tp[N_LEAVES];
        #pragma unroll
        for (int l = 0; l < N_LEAVES; ++l) {
            int node = l + N_INTERNAL;
            float prob = 1.f;
            #pragma unroll
            for (int d = 0; d < DEPTH; ++d) {
                int par = (node - 1) >> 1;
                prob *= (node & 1) ? q_[par] : p_[par];
                node = par;
            }
            tp[l] = prob;
        }
        #pragma unroll
        for (int l = 0; l < N_LEAVES; ++l) {
            const float4* Mv = reinterpret_cast<const float4*>(
                Msm + (t * N_LEAVES + l) * M_STRIDE);
            float4 m0 = Mv[0];
            float4 m1 = Mv[1];
            float2 m2 = *reinterpret_cast<const float2*>(
                Msm + (t * N_LEAVES + l) * M_STRIDE + 8);
            float w = tp[l];
            acc[0] = fmaf(w, m0.x, acc[0]);
            acc[1] = fmaf(w, m0.y, acc[1]);
            acc[2] = fmaf(w, m0.z, acc[2]);
            acc[3] = fmaf(w, m0.w, acc[3]);
            acc[4] = fmaf(w, m1.x, acc[4]);
            acc[5] = fmaf(w, m1.y, acc[5]);
            acc[6] = fmaf(w, m1.z, acc[6]);
            acc[7] = fmaf(w, m1.w, acc[7]);
            acc[8] = fmaf(w, m2.x, acc[8]);
            acc[9] = fmaf(w, m2.y, acc[9]);
        }
    }
    #pragma unroll
    for (int c = 0; c < N_CLASSES; ++c) accout[c] = acc[c];
}

// ===================== main kernel =====================
__global__ __launch_bounds__(THREADS, 2)
void sdt_mma_kernel(const float* __restrict__ x,
                    float* __restrict__ out,
                    int batch)
{
    extern __shared__ char smem[];
    const uint32_t sb = smem_u32(smem);
    const int tid  = threadIdx.x;
    const int lane = tid & 31;
    const int w    = tid >> 5;         // 0..7
    const int mgrp = w >> 1;           // 0..3: rows mgrp*32 .. +31
    const int nh   = w & 1;            // 0/1:  cols nh*56 .. +55

    // ---- copy precomputed B_hi, Mtab, bias into smem ----
    {
        const uint4* src = reinterpret_cast<const uint4*>(gBhi);
        uint4* dst = reinterpret_cast<uint4*>(smem + OFF_BHI);
        #pragma unroll
        for (int i = 0; i < B_BYTES / 16 / THREADS; ++i)
            dst[tid + i * THREADS] = src[tid + i * THREADS];

        float* msm = reinterpret_cast<float*>(smem + OFF_MTAB);
        for (int i = tid; i < N_TREES * N_LEAVES * M_STRIDE; i += THREADS)
            msm[i] = gMtab[i];
        float* bsm = reinterpret_cast<float*>(smem + OFF_BIAS);
        if (tid < N_PAD) bsm[tid] = gBias[tid];
    }

    // ---- stage A: x tile -> bf16 hi/lo, swizzled ----
    {
        const float4* xv = reinterpret_cast<const float4*>(x)
                         + (size_t)blockIdx.x * TILE_M * (INPUT_DIM / 4);
        #pragma unroll
        for (int it = 0; it < TILE_M * (INPUT_DIM / 4) / THREADS; ++it) {
            int idx = tid + it * THREADS;
            int r  = idx >> 5;
            int c4 = idx & 31;
            float4 v = xv[idx];
            __nv_bfloat16 h0 = __float2bfloat16(v.x);
            __nv_bfloat16 h1 = __float2bfloat16(v.y);
            __nv_bfloat16 h2 = __float2bfloat16(v.z);
            __nv_bfloat16 h3 = __float2bfloat16(v.w);
            __nv_bfloat16 l0 = __float2bfloat16(v.x - __bfloat162float(h0));
            __nv_bfloat16 l1 = __float2bfloat16(v.y - __bfloat162float(h1));
            __nv_bfloat16 l2 = __float2bfloat16(v.z - __bfloat162float(h2));
            __nv_bfloat16 l3 = __float2bfloat16(v.w - __bfloat162float(h3));
            uint32_t base = swz(r, c4 >> 1, (c4 & 1) << 3);
            *reinterpret_cast<__nv_bfloat162*>(smem + OFF_AHI + base)     = __nv_bfloat162(h0, h1);
            *reinterpret_cast<__nv_bfloat162*>(smem + OFF_AHI + base + 4) = __nv_bfloat162(h2, h3);
            *reinterpret_cast<__nv_bfloat162*>(smem + OFF_ALO + base)     = __nv_bfloat162(l0, l1);
            *reinterpret_cast<__nv_bfloat162*>(smem + OFF_ALO + base + 4) = __nv_bfloat162(l2, l3);
        }
    }
    __syncthreads();

    // ================= 3-pass bf16-split HMMA mainloop =================
    // A x4 per m16 tile (validated R6): rows mgrp*32 + mt*16
    const int arow_in16 = ((lane >> 3) & 1) * 8 + (lane & 7);
    const int apar      = lane >> 4;
    // B patterns (validated R8): 3 x4 pairs + 1 x2 for the N=56 half
    const int nbase      = nh * 56;
    const int brow_local = ((lane >> 4) & 1) * 8 + (lane & 7);
    const int bpar       = (lane >> 3) & 1;
    const int brow2      = nbase + 48 + (lane & 7);
    const int bpar2      = (lane >> 3) & 1;

    float cc[2][7][4];
    #pragma unroll
    for (int mt = 0; mt < 2; ++mt)
        #pragma unroll
        for (int nt = 0; nt < 7; ++nt)
            #pragma unroll
            for (int i = 0; i < 4; ++i) cc[mt][nt][i] = 0.f;

    const uint32_t sBHI = sb + OFF_BHI;
    const uint32_t sAHI = sb + OFF_AHI;
    const uint32_t sALO = sb + OFF_ALO;

    #pragma unroll 1
    for (int pass = 0; pass < 3; ++pass) {
        const uint32_t Ab = (pass == 1) ? sALO : sAHI;   // Ah, Al, Ah
        const uint32_t Bb = (pass == 2) ? sALO : sBHI;   // Bh, Bh, Bl(in ALO)
        #pragma unroll
        for (int ks = 0; ks < 8; ++ks) {
            const int ch  = ks * 2;
            const int ach = ch + apar;
            uint32_t a[2][4];
            #pragma unroll
            for (int mt = 0; mt < 2; ++mt) {
                int arow = mgrp * 32 + mt * 16 + arow_in16;
                LDSM_X4(a[mt][0], a[mt][1], a[mt][2], a[mt][3],
                        Ab + arow * 256 + ((ach ^ (arow & 7)) << 4));
            }
            #pragma unroll
            for (int j = 0; j < 3; ++j) {
                int brow = nbase + j * 16 + brow_local;
                int bch  = ch + bpar;
                uint32_t b0A, b1A, b0B, b1B;
                LDSM_X4(b0A, b1A, b0B, b1B,
                        Bb + brow * 256 + ((bch ^ (brow & 7)) << 4));
                MMA16816(cc[0][2 * j],     a[0][0], a[0][1], a[0][2], a[0][3], b0A, b1A);
                MMA16816(cc[0][2 * j + 1], a[0][0], a[0][1], a[0][2], a[0][3], b0B, b1B);
                MMA16816(cc[1][2 * j],     a[1][0], a[1][1], a[1][2], a[1][3], b0A, b1A);
                MMA16816(cc[1][2 * j + 1], a[1][0], a[1][1], a[1][2], a[1][3], b0B, b1B);
            }
            {
                uint32_t b0, b1;
                int bch = ch + bpar2;
                LDSM_X2(b0, b1, Bb + brow2 * 256 + ((bch ^ (brow2 & 7)) << 4));
                MMA16816(cc[0][6], a[0][0], a[0][1], a[0][2], a[0][3], b0, b1);
                MMA16816(cc[1][6], a[1][0], a[1][1], a[1][2], a[1][3], b0, b1);
            }
        }
        if (pass == 1) {
            // A_lo consumed; overwrite its region with B_lo for pass 2
            __syncthreads();
            const uint4* src = reinterpret_cast<const uint4*>(gBlo);
            uint4* dst = reinterpret_cast<uint4*>(smem + OFF_ALO);
            #pragma unroll
            for (int i = 0; i < B_BYTES / 16 / THREADS; ++i)
                dst[tid + i * THREADS] = src[tid + i * THREADS];
            __syncthreads();
        }
    }

    // ---- scatter accumulators to z tile (A regions dead) ----
    __syncthreads();
    float* zsm = reinterpret_cast<float*>(smem + OFF_ZS);
    {
        const int rsub  = lane >> 2;
        const int cbase = nbase + ((lane & 3) << 1);
        #pragma unroll
        for (int mt = 0; mt < 2; ++mt) {
            int row = mgrp * 32 + mt * 16 + rsub;
            #pragma unroll
            for (int nt = 0; nt < 7; ++nt) {
                int col = nt * 8 + cbase;
                zsm[row * Z_STRIDE + col]           = cc[mt][nt][0];
                zsm[row * Z_STRIDE + col + 1]       = cc[mt][nt][1];
                zsm[(row + 8) * Z_STRIDE + col]     = cc[mt][nt][2];
                zsm[(row + 8) * Z_STRIDE + col + 1] = cc[mt][nt][3];
            }
        }
    }
    __syncthreads();

    // ---- tree epilogue: all 256 threads; row = tid&127, tree-half = tid>>7 ----
    {
        const float* Msm = reinterpret_cast<const float*>(smem + OFF_MTAB);
        const float* bsm = reinterpret_cast<const float*>(smem + OFF_BIAS);
        float* osm = reinterpret_cast<float*>(smem + OFF_OSM);  // [2][128][10]

        const int r    = tid & 127;
        const int half = tid >> 7;
        const float* zrow = zsm + r * Z_STRIDE;

        float acc[N_CLASSES];
        if (half == 0) tree_epi<0, 8>(zrow, bsm, Msm, acc);
        else           tree_epi<8, 15>(zrow, bsm, Msm, acc);

        #pragma unroll
        for (int c = 0; c < N_CLASSES; ++c)
            osm[(half * TILE_M + r) * N_CLASSES + c] = acc[c];
    }
    __syncthreads();

    // ---- sum halves, then coalesced store ----
    {
        float* osm = reinterpret_cast<float*>(smem + OFF_OSM);
        if (tid < TILE_M) {
            #pragma unroll
            for (int c = 0; c < N_CLASSES; ++c)
                osm[tid * N_CLASSES + c] += osm[(TILE_M + tid) * N_CLASSES + c];
        }
        __syncthreads();
        const uint4* osv = reinterpret_cast<const uint4*>(osm);
        uint4* og = reinterpret_cast<uint4*>(out + (size_t)blockIdx.x * TILE_M * N_CLASSES);
        #pragma unroll
        for (int i = tid; i < TILE_M * N_CLASSES / 4; i += THREADS)
            og[i] = osv[i];
    }
}

extern "C" void kernel_launch(void* const* d_in, const int* in_sizes, int n_in,
                              void* d_out, int out_size)
{
    const float* x      = (const float*)d_in[0];
    const float* params = (const float*)d_in[1];
    float* out          = (float*)d_out;

    int batch = in_sizes[0] / INPUT_DIM;

    cudaFuncSetAttribute(sdt_mma_kernel,
                         cudaFuncAttributeMaxDynamicSharedMemorySize,
                         SMEM_TOTAL);

    sdt_setup_kernel<<<1, 128>>>(params);

    int grid = (batch + TILE_M - 1) / TILE_M;
    sdt_mma_kernel<<<grid, THREADS, SMEM_TOTAL>>>(x, out, batch);
}